// round 16
// baseline (speedup 1.0000x reference)
#include <cuda_runtime.h>

#define KTAGS 48
#define TLEN 1024
#define STOPID 47
#define NEGV (-10000.0f)

__device__ __forceinline__ unsigned long long pk2(float lo, float hi) {
    unsigned long long r;
    asm("mov.b64 %0, {%1, %2};" : "=l"(r) : "f"(lo), "f"(hi));
    return r;
}
__device__ __forceinline__ void upk2(unsigned long long v, float& lo, float& hi) {
    asm("mov.b64 {%0, %1}, %2;" : "=f"(lo), "=f"(hi) : "l"(v));
}
// d = a*b + d  (packed f32x2 -> SASS FFMA2)
__device__ __forceinline__ void fma2(unsigned long long& d, unsigned long long a, unsigned long long b) {
    asm("fma.rn.f32x2 %0, %1, %2, %0;" : "+l"(d) : "l"(a), "l"(b));
}
__device__ __forceinline__ void add2(unsigned long long& d, unsigned long long a) {
    asm("add.rn.f32x2 %0, %0, %1;" : "+l"(d) : "l"(a));
}

// Renorm: exact power-of-2 scale from the warp-max exponent. All v >= 0.
// Every row of v lives on at least one lane, so the REDUX max is global.
__device__ __forceinline__ void renorm3(float& v0, float& v1, float& vB, int& Mint) {
    float lmax = fmaxf(fmaxf(v0, v1), vB);
    unsigned mxb = __reduce_max_sync(0xffffffffu, __float_as_uint(lmax));
    int ebx = (int)(mxb >> 23);                              // biased exponent of max
    float r = __uint_as_float((unsigned)(254 - ebx) << 23);  // 2^(127-eb)
    v0 *= r; v1 *= r; vB *= r;
    Mint += ebx - 127;
}

// Zero-duplication decomposition: lane l owns rows r0=(l&15), r1=16+(l&15),
// rB=32+(l&15), but only the j-half [24*(l>=16), +24). 3 half-dots of 12 FFMA2
// each (36 FFMA2 = 72 MACs = 2304/32, the no-duplication floor), merged with
// 3 symmetric shfl_xor(16). Each lane loads only its 24-value v half (6 LDS.128).
// FWD: alpha' = D_t E alpha  over emissions s=1..511 (t=s).
// !FWD: beta' = E^T D_t beta over emissions s=1..512 (t=1024-s).
// Renorm every 8 steps (worst-case growth ~e^64 < fp32 max e^88) + final renorm.
template <bool FWD>
__device__ __forceinline__ void run_chain(
    const float* __restrict__ eb, const float* __restrict__ mb,
    const unsigned long long* E0, const unsigned long long* E1,
    const unsigned long long* EBr,
    float& v0, float& v1, float& vB, int& Mint,
    float* __restrict__ vbuf0, float* __restrict__ vbuf1,
    int lane)
{
    const int l16 = lane & 15;
    const bool lo = (lane < 16);
    const int r0 = l16, r1 = 16 + l16, rB = 32 + l16;
    const int jb = lo ? 0 : 24;                    // j-half base

    float n0[4], n1[4], nB[4], nM[4];
    #pragma unroll
    for (int u = 0; u < 4; ++u) {
        int s = 1 + u;
        int t = FWD ? s : (TLEN - s);
        n0[u] = eb[t * KTAGS + r0];
        n1[u] = eb[t * KTAGS + r1];
        nB[u] = eb[t * KTAGS + rB];
        nM[u] = mb[t];
    }

    float* vcur = vbuf0;
    float* vnxt = vbuf1;
    for (int base = 1; base < 513; base += 4) {
        // hoist the group's exps off the per-step chain
        float e0[4], e1[4], eB[4], cM[4];
        #pragma unroll
        for (int u = 0; u < 4; ++u) {
            e0[u] = __expf(n0[u]);
            e1[u] = __expf(n1[u]);
            eB[u] = __expf(nB[u]);
            cM[u] = nM[u];
        }
        #pragma unroll
        for (int u = 0; u < 4; ++u) {
            int s = base + 4 + u;                  // max 516; t valid both directions
            int t = FWD ? s : (TLEN - s);
            n0[u] = eb[t * KTAGS + r0];
            n1[u] = eb[t * KTAGS + r1];
            nB[u] = eb[t * KTAGS + rB];
            nM[u] = mb[t];
        }
        #pragma unroll
        for (int u = 0; u < 4; ++u) {
            int s = base + u;
            if (FWD && s > 511) break;             // fwd: 511 loop steps; bwd: 512

            // fwd stores v, multiplies emission after matvec (alpha' = D E alpha)
            // bwd stores v*exp(e), matvec only (beta' = E^T D beta)
            float w0 = FWD ? v0 : v0 * e0[u];
            float w1 = FWD ? v1 : v1 * e1[u];
            float wB = FWD ? vB : vB * eB[u];
            if (lo) { vcur[r0] = w0; vcur[r1] = w1; }
            else    { vcur[rB] = wB; }
            __syncwarp();

            // each lane loads only its j-half: 24 floats = 6 LDS.128
            const ulonglong2* vp = (const ulonglong2*)(vcur + jb);
            ulonglong2 w[6];
            #pragma unroll
            for (int k = 0; k < 6; ++k) w[k] = vp[k];

            unsigned long long a0[2] = {0, 0}, a1[2] = {0, 0}, aB[2] = {0, 0};
            #pragma unroll
            for (int k = 0; k < 6; ++k) {
                fma2(a0[0], E0[2 * k],     w[k].x);
                fma2(a0[1], E0[2 * k + 1], w[k].y);
                fma2(a1[0], E1[2 * k],     w[k].x);
                fma2(a1[1], E1[2 * k + 1], w[k].y);
                fma2(aB[0], EBr[2 * k],     w[k].x);
                fma2(aB[1], EBr[2 * k + 1], w[k].y);
            }
            add2(a0[0], a0[1]);
            add2(a1[0], a1[1]);
            add2(aB[0], aB[1]);

            float l, h;
            upk2(a0[0], l, h); float d0h = l + h;
            upk2(a1[0], l, h); float d1h = l + h;
            upk2(aB[0], l, h); float dBh = l + h;
            // merge the two j-halves (symmetric: both halves get the full dot)
            float d0 = d0h + __shfl_xor_sync(0xffffffffu, d0h, 16);
            float d1 = d1h + __shfl_xor_sync(0xffffffffu, d1h, 16);
            float dB = dBh + __shfl_xor_sync(0xffffffffu, dBh, 16);

            float raw0 = FWD ? d0 * e0[u] : d0;
            float raw1 = FWD ? d1 * e1[u] : d1;
            float rawB = FWD ? dB * eB[u] : dB;
            bool live = (cM[u] != 0.f);
            v0 = live ? raw0 : v0;
            v1 = live ? raw1 : v1;
            vB = live ? rawB : vB;

            // renorm every 8 steps: groups base=5,13,... at u==3 -> s=8,16,...
            if ((u == 3) && ((base & 4) != 0))
                renorm3(v0, v1, vB, Mint);

            float* tp = vcur; vcur = vnxt; vnxt = tp;
        }
    }
    renorm3(v0, v1, vB, Mint);                     // bound v before alpha*beta combine
}

// One block = 4 batches, 8 warps. Warp w: batch blk*4 + (w>>1), fwd if (w&1)==0.
// Z = Mf + Mb + log(sum_i alphaHat_i * betaHat_i).
__global__ __launch_bounds__(256, 1)
void CRF_29265907155259_kernel(const float* __restrict__ h_tag,
                               const float* __restrict__ mask,
                               const float* __restrict__ trans,
                               float* __restrict__ out, int B)
{
    __shared__ __align__(16) float vbuf[8][2][KTAGS];   // [warp][pingpong][tag]
    __shared__ float cbuf[8][KTAGS];
    __shared__ double Msh[8];

    const int lane = threadIdx.x & 31;
    const int warp = threadIdx.x >> 5;
    const bool fwd = ((warp & 1) == 0);
    int b = blockIdx.x * 4 + (warp >> 1);
    bool valid = (b < B);
    if (!valid) b = B - 1;                 // clamp (duplicate work) so __syncthreads is safe

    const int l16 = lane & 15;
    const bool lo = (lane < 16);
    const int r0 = l16, r1 = 16 + l16, rB = 32 + l16;
    const int jb = lo ? 0 : 24;

    // ---- E = exp(trans) (fwd) or exp(trans)^T (bwd): per-lane j-half rows ----
    unsigned long long E0[12], E1[12], EBr[12];
    float rs0h = 0.f, rs1h = 0.f, rsBh = 0.f;
    #pragma unroll
    for (int k = 0; k < 12; ++k) {
        int j0 = jb + 2 * k, j1 = jb + 2 * k + 1;
        float a0 = __expf(fwd ? trans[r0 * KTAGS + j0] : trans[j0 * KTAGS + r0]);
        float a1 = __expf(fwd ? trans[r0 * KTAGS + j1] : trans[j1 * KTAGS + r0]);
        rs0h += a0 + a1;
        E0[k] = pk2(a0, a1);
        float b0 = __expf(fwd ? trans[r1 * KTAGS + j0] : trans[j0 * KTAGS + r1]);
        float b1 = __expf(fwd ? trans[r1 * KTAGS + j1] : trans[j1 * KTAGS + r1]);
        rs1h += b0 + b1;
        E1[k] = pk2(b0, b1);
        float c0 = __expf(fwd ? trans[rB * KTAGS + j0] : trans[j0 * KTAGS + rB]);
        float c1 = __expf(fwd ? trans[rB * KTAGS + j1] : trans[j1 * KTAGS + rB]);
        rsBh += c0 + c1;
        EBr[k] = pk2(c0, c1);
    }
    const float rs0 = rs0h + __shfl_xor_sync(0xffffffffu, rs0h, 16);
    const float rs1 = rs1h + __shfl_xor_sync(0xffffffffu, rs1h, 16);
    const float rsB = rsBh + __shfl_xor_sync(0xffffffffu, rsBh, 16);

    const float* eb = h_tag + (size_t)b * TLEN * KTAGS;
    const float* mb = mask + (size_t)b * TLEN;

    float v0, v1, vB;
    double M0;
    int Mint = 0;

    if (fwd) {
        // ---- special step t = 0 (log domain, exact; exp-domain would underflow) ----
        float m0 = mb[0];
        float s0 = NEGV + __logf(1.0f + rs0) + eb[r0];
        float s1 = NEGV + __logf(1.0f + rs1) + eb[r1];
        float sB = NEGV + __logf(1.0f + rsB) + eb[rB];
        s0 = (m0 != 0.f) ? s0 : NEGV;                            // rows 0..31: never STOP
        s1 = (m0 != 0.f) ? s1 : NEGV;
        sB = (m0 != 0.f) ? sB : ((rB == STOPID) ? 0.f : NEGV);
        float loc = fmaxf(fmaxf(s0, s1), sB);
        #pragma unroll
        for (int o = 16; o; o >>= 1)
            loc = fmaxf(loc, __shfl_xor_sync(0xffffffffu, loc, o));
        M0 = (double)loc;
        v0 = __expf(s0 - loc);
        v1 = __expf(s1 - loc);
        vB = __expf(sB - loc);
    } else {
        // beta_{1023}(i) = exp(trans[STOP, i]); values O(e^4) -> no scaling needed
        v0 = __expf(trans[STOPID * KTAGS + r0]);
        v1 = __expf(trans[STOPID * KTAGS + r1]);
        vB = __expf(trans[STOPID * KTAGS + rB]);
        M0 = 0.0;
    }

    if (fwd)
        run_chain<true >(eb, mb, E0, E1, EBr, v0, v1, vB, Mint,
                         &vbuf[warp][0][0], &vbuf[warp][1][0], lane);
    else
        run_chain<false>(eb, mb, E0, E1, EBr, v0, v1, vB, Mint,
                         &vbuf[warp][0][0], &vbuf[warp][1][0], lane);

    // ---- combine: Z = Mf + Mb + log(sum_i alpha_i * beta_i) ----
    if (lo) { cbuf[warp][r0] = v0; cbuf[warp][r1] = v1; }
    else    { cbuf[warp][rB] = vB; }
    if (lane == 0) Msh[warp] = M0 + (double)Mint * 0.6931471805599453;
    __syncthreads();

    if (fwd) {
        float fin = cbuf[warp][lane] * cbuf[warp + 1][lane];
        if (lo) fin += cbuf[warp][32 + lane] * cbuf[warp + 1][32 + lane];
        #pragma unroll
        for (int o = 16; o; o >>= 1)
            fin += __shfl_xor_sync(0xffffffffu, fin, o);
        if (lane == 0 && valid)
            out[b] = (float)(Msh[warp] + Msh[warp + 1] + (double)__logf(fin));
    }
}

extern "C" void kernel_launch(void* const* d_in, const int* in_sizes, int n_in,
                              void* d_out, int out_size) {
    const float* h_tag = (const float*)d_in[0];
    const float* msk   = (const float*)d_in[1];
    const float* trans = (const float*)d_in[2];
    float* out = (float*)d_out;
    int B = in_sizes[0] / (TLEN * KTAGS);
    int blocks = (B + 3) / 4;
    CRF_29265907155259_kernel<<<blocks, 256>>>(h_tag, msk, trans, out, B);
}